// round 5
// baseline (speedup 1.0000x reference)
#include <cuda_runtime.h>
#include <math.h>

#define C 96
#define FOURC 384
#define NN 4096

// ---------------- device scratch (static, no allocations) ----------------
__device__ __align__(16) float g_G0[C * C];
__device__ __align__(16) float g_G1[C * C];
__device__ __align__(16) float g_G2[C * C];
__device__ __align__(16) float g_x0[NN * C];          // 1.5 MB
__device__ __align__(16) float g_x1[3 * NN * C];      // 4.5 MB  [m][n*C+u]
__device__ __align__(16) float g_q [NN * C];          // 1.5 MB
__device__ __align__(16) float g_z [NN * C];          // 1.5 MB
__device__ __align__(16) float g_nrm[NN * C];         // 1.5 MB
__device__ __align__(16) float g_tpw[NN * FOURC];     // 6 MB

// ---------------------------------------------------------------------------
// Precompute: collapse C x C x C fctp tensors against rank-1 y-factors.
// ---------------------------------------------------------------------------
__global__ void precompute_kernel(const float* __restrict__ W00,
                                  const float* __restrict__ W11,
                                  const float* __restrict__ Wl2_0,
                                  const float* __restrict__ bl2_0,
                                  const float* __restrict__ Wl2_1)
{
    int idx = blockIdx.x * 256 + threadIdx.x;   // (u, w), w fastest
    if (idx >= C * C) return;
    int u = idx / C;
    int w = idx - u * C;
    const float* p00 = W00 + u * C * C + w;
    const float* p11 = W11 + u * C * C + w;
    float a = 0.f, b = 0.f, c = 0.f;
    #pragma unroll 4
    for (int v = 0; v < C; v++) {
        float e00 = p00[v * C];
        float e11 = p11[v * C];
        a = fmaf(Wl2_0[v], e00, a);
        b = fmaf(bl2_0[v], e00, b);
        c = fmaf(Wl2_1[v], e11, c);
    }
    const float inv_s2 = 1.0f / sqrtf(2.0f * C * C);
    const float inv_s3 = 1.0f / sqrtf(3.0f);
    g_G0[idx] = a * inv_s2;
    g_G1[idx] = b * inv_s2;
    g_G2[idx] = c * inv_s2 * inv_s3;
}

// ---------------------------------------------------------------------------
// Helpers
// ---------------------------------------------------------------------------
template<int NT>
__device__ __forceinline__ void stage4(float* dst, const float* __restrict__ src, int n4)
{
    float4* d = reinterpret_cast<float4*>(dst);
    const float4* s = reinterpret_cast<const float4*>(src);
    for (int i = threadIdx.x; i < n4; i += NT) d[i] = s[i];
}

__device__ __forceinline__ void loadw12(float w[12], const float* wrow)
{
    *reinterpret_cast<float4*>(w)     = *reinterpret_cast<const float4*>(wrow);
    *reinterpret_cast<float4*>(w + 4) = *reinterpret_cast<const float4*>(wrow + 4);
    *reinterpret_cast<float4*>(w + 8) = *reinterpret_cast<const float4*>(wrow + 8);
}

__device__ __forceinline__ void fma12(float acc[12], float a, const float* wrow)
{
    float w[12];
    loadw12(w, wrow);
    #pragma unroll
    for (int j = 0; j < 12; j++) acc[j] = fmaf(a, w[j], acc[j]);
}

__device__ __forceinline__ void fma12_tri(float c0[12], float c1[12], float c2[12],
                                          float s0, float s1, float s2, const float* wrow)
{
    float w[12];
    loadw12(w, wrow);
    #pragma unroll
    for (int j = 0; j < 12; j++) {
        c0[j] = fmaf(s0, w[j], c0[j]);
        c1[j] = fmaf(s1, w[j], c1[j]);
        c2[j] = fmaf(s2, w[j], c2[j]);
    }
}

__device__ __forceinline__ void store12(float* dst, const float v[12])
{
    reinterpret_cast<float4*>(dst)[0] = reinterpret_cast<const float4*>(v)[0];
    reinterpret_cast<float4*>(dst)[1] = reinterpret_cast<const float4*>(v)[1];
    reinterpret_cast<float4*>(dst)[2] = reinterpret_cast<const float4*>(v)[2];
}

// Common thread mapping for C-col GEMM kernels: TILE=16 nodes, 128 threads.
// n = tid>>3 (node in tile), v0 = (tid&7)*12 (output columns).
#define GEMM_TILE 16
#define GEMM_NT   128
#define GEMM_GRID (NN / GEMM_TILE)   // 256

// ---------------------------------------------------------------------------
// K1: x0 = nf0 @ Wl1_0 * invC ; x1_m = nf1_m @ Wl1_1 * invC ; q = sum_m x1_m p1_m
// ---------------------------------------------------------------------------
__global__ void __launch_bounds__(GEMM_NT)
k1_kernel(const float* __restrict__ nf, const float* __restrict__ pot,
          const float* __restrict__ Wl1_0, const float* __restrict__ Wl1_1)
{
    extern __shared__ __align__(16) float sm[];
    float* B  = sm;
    float* B2 = sm + C * C;
    const int tid = threadIdx.x;
    const int n   = tid >> 3;
    const int v0  = (tid & 7) * 12;
    const int row = blockIdx.x * GEMM_TILE + n;
    const float INVC = 1.0f / sqrtf((float)C);

    stage4<GEMM_NT>(B,  Wl1_0, C * C / 4);
    stage4<GEMM_NT>(B2, Wl1_1, C * C / 4);
    __syncthreads();

    // x0
    {
        float acc[12];
        #pragma unroll
        for (int j = 0; j < 12; j++) acc[j] = 0.f;
        const float* ra = nf + (size_t)row * FOURC;
        for (int u = 0; u < C; u += 4) {
            float4 a4 = *reinterpret_cast<const float4*>(ra + u);
            fma12(acc, a4.x, B + (u + 0) * C + v0);
            fma12(acc, a4.y, B + (u + 1) * C + v0);
            fma12(acc, a4.z, B + (u + 2) * C + v0);
            fma12(acc, a4.w, B + (u + 3) * C + v0);
        }
        float o[12];
        #pragma unroll
        for (int j = 0; j < 12; j++) o[j] = acc[j] * INVC;
        store12(g_x0 + (size_t)row * C + v0, o);
    }

    // x1 (3 planes) + q
    {
        float c0[12], c1[12], c2[12];
        #pragma unroll
        for (int j = 0; j < 12; j++) { c0[j] = 0.f; c1[j] = 0.f; c2[j] = 0.f; }
        const float* rb = nf + (size_t)row * FOURC + C;
        for (int u = 0; u < C; u += 4) {
            float4 a0 = *reinterpret_cast<const float4*>(rb + u * 3);
            float4 a1 = *reinterpret_cast<const float4*>(rb + u * 3 + 4);
            float4 a2 = *reinterpret_cast<const float4*>(rb + u * 3 + 8);
            fma12_tri(c0, c1, c2, a0.x, a0.y, a0.z, B2 + (u + 0) * C + v0);
            fma12_tri(c0, c1, c2, a0.w, a1.x, a1.y, B2 + (u + 1) * C + v0);
            fma12_tri(c0, c1, c2, a1.z, a1.w, a2.x, B2 + (u + 2) * C + v0);
            fma12_tri(c0, c1, c2, a2.y, a2.z, a2.w, B2 + (u + 3) * C + v0);
        }
        float p1 = pot[row * 4 + 1], p2 = pot[row * 4 + 2], p3 = pot[row * 4 + 3];
        float e0[12], e1[12], e2[12], qv[12];
        #pragma unroll
        for (int j = 0; j < 12; j++) {
            e0[j] = c0[j] * INVC; e1[j] = c1[j] * INVC; e2[j] = c2[j] * INVC;
            qv[j] = e0[j] * p1 + e1[j] * p2 + e2[j] * p3;
        }
        store12(g_x1 + 0 * (size_t)NN * C + (size_t)row * C + v0, e0);
        store12(g_x1 + 1 * (size_t)NN * C + (size_t)row * C + v0, e1);
        store12(g_x1 + 2 * (size_t)NN * C + (size_t)row * C + v0, e2);
        store12(g_q + (size_t)row * C + v0, qv);
    }
}

// ---------------------------------------------------------------------------
// K2a: z = p0*(x0@G0) + x0@G1
// ---------------------------------------------------------------------------
__global__ void __launch_bounds__(GEMM_NT)
k2a_kernel(const float* __restrict__ pot)
{
    extern __shared__ __align__(16) float sm[];
    float* B  = sm;
    float* B2 = sm + C * C;
    const int tid = threadIdx.x;
    const int n   = tid >> 3;
    const int v0  = (tid & 7) * 12;
    const int row = blockIdx.x * GEMM_TILE + n;

    stage4<GEMM_NT>(B,  g_G0, C * C / 4);
    stage4<GEMM_NT>(B2, g_G1, C * C / 4);
    __syncthreads();

    float s0[12], s1[12];
    #pragma unroll
    for (int j = 0; j < 12; j++) { s0[j] = 0.f; s1[j] = 0.f; }
    const float* xr = g_x0 + (size_t)row * C;
    for (int u = 0; u < C; u += 4) {
        float4 xv = *reinterpret_cast<const float4*>(xr + u);
        fma12(s0, xv.x, B + (u + 0) * C + v0);
        fma12(s1, xv.x, B2 + (u + 0) * C + v0);
        fma12(s0, xv.y, B + (u + 1) * C + v0);
        fma12(s1, xv.y, B2 + (u + 1) * C + v0);
        fma12(s0, xv.z, B + (u + 2) * C + v0);
        fma12(s1, xv.z, B2 + (u + 2) * C + v0);
        fma12(s0, xv.w, B + (u + 3) * C + v0);
        fma12(s1, xv.w, B2 + (u + 3) * C + v0);
    }
    float p0 = pot[row * 4];
    float o[12];
    #pragma unroll
    for (int j = 0; j < 12; j++) o[j] = p0 * s0[j] + s1[j];
    store12(g_z + (size_t)row * C + v0, o);
}

// ---------------------------------------------------------------------------
// K2b: norms = (z + q@G2)^2
// ---------------------------------------------------------------------------
__global__ void __launch_bounds__(GEMM_NT)
k2b_kernel()
{
    extern __shared__ __align__(16) float sm[];
    float* B = sm;
    const int tid = threadIdx.x;
    const int n   = tid >> 3;
    const int v0  = (tid & 7) * 12;
    const int row = blockIdx.x * GEMM_TILE + n;

    stage4<GEMM_NT>(B, g_G2, C * C / 4);
    __syncthreads();

    float t[12];
    #pragma unroll
    for (int j = 0; j < 12; j++) t[j] = 0.f;
    const float* qr = g_q + (size_t)row * C;
    for (int u = 0; u < C; u += 4) {
        float4 qv = *reinterpret_cast<const float4*>(qr + u);
        fma12(t, qv.x, B + (u + 0) * C + v0);
        fma12(t, qv.y, B + (u + 1) * C + v0);
        fma12(t, qv.z, B + (u + 2) * C + v0);
        fma12(t, qv.w, B + (u + 3) * C + v0);
    }
    const float* zr = g_z + (size_t)row * C + v0;
    float o[12];
    #pragma unroll
    for (int j = 0; j < 12; j++) {
        float v = zr[j] + t[j];
        o[j] = v * v;
    }
    store12(g_nrm + (size_t)row * C + v0, o);
}

// ---------------------------------------------------------------------------
// K3: MLP  norms -> tp_w   (TILE=32 nodes, 256 threads)
// ---------------------------------------------------------------------------
#define K3_TILE 32
#define K3_NT   256
__global__ void __launch_bounds__(K3_NT)
k3_kernel(const float* __restrict__ Wm1, const float* __restrict__ Wm2,
          const float* __restrict__ Wm3, const float* __restrict__ Wm4,
          float silu_cst)
{
    extern __shared__ __align__(16) float sm[];
    float* W1 = sm;            // 96x16  = 1536
    float* W2 = sm + 1536;     // 16x16  = 256
    float* W3 = sm + 1792;     // 16x16  = 256
    float* W4 = sm + 2048;     // 16x384 = 6144
    float* H1 = sm + 8192;     // 32x16
    float* H2 = sm + 8704;     // 32x16
    const int tid  = threadIdx.x;
    const int base = blockIdx.x * K3_TILE;
    const float INVC = 1.0f / sqrtf((float)C);
    const float cst = silu_cst;

    stage4<K3_NT>(W1, Wm1, 1536 / 4);
    stage4<K3_NT>(W2, Wm2, 256 / 4);
    stage4<K3_NT>(W3, Wm3, 256 / 4);
    stage4<K3_NT>(W4, Wm4, 6144 / 4);
    __syncthreads();

    // h1
    #pragma unroll
    for (int idx = tid; idx < K3_TILE * 16; idx += K3_NT) {
        int nn = idx >> 4, j = idx & 15;
        const float* nr = g_nrm + (size_t)(base + nn) * C;
        float s = 0.f;
        #pragma unroll 8
        for (int u = 0; u < C; u++) s = fmaf(nr[u], W1[u * 16 + j], s);
        s *= INVC;
        H1[idx] = cst * s / (1.0f + expf(-s));
    }
    __syncthreads();
    // h2
    #pragma unroll
    for (int idx = tid; idx < K3_TILE * 16; idx += K3_NT) {
        int nn = idx >> 4, j = idx & 15;
        float s = 0.f;
        #pragma unroll
        for (int k = 0; k < 16; k++) s = fmaf(H1[nn * 16 + k], W2[k * 16 + j], s);
        s *= 0.25f;
        H2[idx] = cst * s / (1.0f + expf(-s));
    }
    __syncthreads();
    // h3
    #pragma unroll
    for (int idx = tid; idx < K3_TILE * 16; idx += K3_NT) {
        int nn = idx >> 4, j = idx & 15;
        float s = 0.f;
        #pragma unroll
        for (int k = 0; k < 16; k++) s = fmaf(H2[nn * 16 + k], W3[k * 16 + j], s);
        s *= 0.25f;
        H1[idx] = cst * s / (1.0f + expf(-s));
    }
    __syncthreads();
    // tp_w = h3 @ Wm4 * 0.25
    for (int idx = tid; idx < K3_TILE * FOURC; idx += K3_NT) {
        int nn = idx / FOURC, j = idx - nn * FOURC;
        float s = 0.f;
        #pragma unroll
        for (int k = 0; k < 16; k++) s = fmaf(H1[nn * 16 + k], W4[k * FOURC + j], s);
        g_tpw[(size_t)(base + nn) * FOURC + j] = s * 0.25f;
    }
}

// ---------------------------------------------------------------------------
// K4a: out1[n,v,m] = (p1m * ((w01*x0)@Wo1a)[v] + p0 * ((w10*x1_m)@Wo1b)[v]) * norm_out
// ---------------------------------------------------------------------------
__global__ void __launch_bounds__(GEMM_NT)
k4a_kernel(const float* __restrict__ pot,
           const float* __restrict__ Wo1a, const float* __restrict__ Wo1b,
           float* __restrict__ out)
{
    extern __shared__ __align__(16) float sm[];
    float* B  = sm;
    float* B2 = sm + C * C;
    const int tid = threadIdx.x;
    const int n   = tid >> 3;
    const int v0  = (tid & 7) * 12;
    const int row = blockIdx.x * GEMM_TILE + n;
    const float NORM_OUT = 1.0f / sqrtf(2.0f * C);

    stage4<GEMM_NT>(B,  Wo1a, C * C / 4);
    stage4<GEMM_NT>(B2, Wo1b, C * C / 4);
    __syncthreads();

    const float* tp = g_tpw + (size_t)row * FOURC;
    const float* xr = g_x0 + (size_t)row * C;

    float sa[12];
    #pragma unroll
    for (int j = 0; j < 12; j++) sa[j] = 0.f;
    for (int u = 0; u < C; u += 4) {
        float4 wv = *reinterpret_cast<const float4*>(tp + C + u);
        float4 xv = *reinterpret_cast<const float4*>(xr + u);
        fma12(sa, wv.x * xv.x, B + (u + 0) * C + v0);
        fma12(sa, wv.y * xv.y, B + (u + 1) * C + v0);
        fma12(sa, wv.z * xv.z, B + (u + 2) * C + v0);
        fma12(sa, wv.w * xv.w, B + (u + 3) * C + v0);
    }

    float c0[12], c1[12], c2[12];
    #pragma unroll
    for (int j = 0; j < 12; j++) { c0[j] = 0.f; c1[j] = 0.f; c2[j] = 0.f; }
    const float* x10 = g_x1 + 0 * (size_t)NN * C + (size_t)row * C;
    const float* x11 = g_x1 + 1 * (size_t)NN * C + (size_t)row * C;
    const float* x12 = g_x1 + 2 * (size_t)NN * C + (size_t)row * C;
    for (int u = 0; u < C; u += 4) {
        float4 wv = *reinterpret_cast<const float4*>(tp + 2 * C + u);
        float4 a0 = *reinterpret_cast<const float4*>(x10 + u);
        float4 a1 = *reinterpret_cast<const float4*>(x11 + u);
        float4 a2 = *reinterpret_cast<const float4*>(x12 + u);
        fma12_tri(c0, c1, c2, wv.x * a0.x, wv.x * a1.x, wv.x * a2.x, B2 + (u + 0) * C + v0);
        fma12_tri(c0, c1, c2, wv.y * a0.y, wv.y * a1.y, wv.y * a2.y, B2 + (u + 1) * C + v0);
        fma12_tri(c0, c1, c2, wv.z * a0.z, wv.z * a1.z, wv.z * a2.z, B2 + (u + 2) * C + v0);
        fma12_tri(c0, c1, c2, wv.w * a0.w, wv.w * a1.w, wv.w * a2.w, B2 + (u + 3) * C + v0);
    }

    float p0 = pot[row * 4 + 0];
    float p1 = pot[row * 4 + 1], p2 = pot[row * 4 + 2], p3 = pot[row * 4 + 3];
    float o[36];
    #pragma unroll
    for (int j = 0; j < 12; j++) {
        float s = sa[j];
        o[j * 3 + 0] = (p1 * s + p0 * c0[j]) * NORM_OUT;
        o[j * 3 + 1] = (p2 * s + p0 * c1[j]) * NORM_OUT;
        o[j * 3 + 2] = (p3 * s + p0 * c2[j]) * NORM_OUT;
    }
    float4* dst = reinterpret_cast<float4*>(out + (size_t)row * FOURC + C + v0 * 3);
    const float4* src = reinterpret_cast<const float4*>(o);
    #pragma unroll
    for (int i = 0; i < 9; i++) dst[i] = src[i];
}

// ---------------------------------------------------------------------------
// K4b: out0 = ( p0*((w00*x0)@Wo0a) + inv_sqrt3*((w11*q)@Wo0b) ) * norm_out
// ---------------------------------------------------------------------------
__global__ void __launch_bounds__(GEMM_NT)
k4b_kernel(const float* __restrict__ pot,
           const float* __restrict__ Wo0a, const float* __restrict__ Wo0b,
           float* __restrict__ out)
{
    extern __shared__ __align__(16) float sm[];
    float* B  = sm;
    float* B2 = sm + C * C;
    const int tid = threadIdx.x;
    const int n   = tid >> 3;
    const int v0  = (tid & 7) * 12;
    const int row = blockIdx.x * GEMM_TILE + n;
    const float NORM_OUT  = 1.0f / sqrtf(2.0f * C);
    const float INV_SQRT3 = 1.0f / sqrtf(3.0f);

    stage4<GEMM_NT>(B,  Wo0a, C * C / 4);
    stage4<GEMM_NT>(B2, Wo0b, C * C / 4);
    __syncthreads();

    const float* tp = g_tpw + (size_t)row * FOURC;
    const float* xr = g_x0 + (size_t)row * C;
    const float* qr = g_q + (size_t)row * C;

    float o1[12], o2[12];
    #pragma unroll
    for (int j = 0; j < 12; j++) { o1[j] = 0.f; o2[j] = 0.f; }
    for (int u = 0; u < C; u += 4) {
        float4 w0 = *reinterpret_cast<const float4*>(tp + u);
        float4 w3 = *reinterpret_cast<const float4*>(tp + 3 * C + u);
        float4 xv = *reinterpret_cast<const float4*>(xr + u);
        float4 qv = *reinterpret_cast<const float4*>(qr + u);
        fma12(o1, w0.x * xv.x, B + (u + 0) * C + v0);
        fma12(o2, w3.x * qv.x, B2 + (u + 0) * C + v0);
        fma12(o1, w0.y * xv.y, B + (u + 1) * C + v0);
        fma12(o2, w3.y * qv.y, B2 + (u + 1) * C + v0);
        fma12(o1, w0.z * xv.z, B + (u + 2) * C + v0);
        fma12(o2, w3.z * qv.z, B2 + (u + 2) * C + v0);
        fma12(o1, w0.w * xv.w, B + (u + 3) * C + v0);
        fma12(o2, w3.w * qv.w, B2 + (u + 3) * C + v0);
    }
    float p0 = pot[row * 4];
    float o[12];
    #pragma unroll
    for (int j = 0; j < 12; j++)
        o[j] = (p0 * o1[j] + o2[j] * INV_SQRT3) * NORM_OUT;
    store12(out + (size_t)row * FOURC + v0, o);
}

// ---------------------------------------------------------------------------
extern "C" void kernel_launch(void* const* d_in, const int* in_sizes, int n_in,
                              void* d_out, int out_size)
{
    const float* nf    = (const float*)d_in[0];
    const float* pot   = (const float*)d_in[1];
    const float* Wl1_0 = (const float*)d_in[2];
    const float* Wl1_1 = (const float*)d_in[3];
    const float* Wl2_0 = (const float*)d_in[4];
    const float* bl2_0 = (const float*)d_in[5];
    const float* Wl2_1 = (const float*)d_in[6];
    const float* W00   = (const float*)d_in[7];
    const float* W11   = (const float*)d_in[8];
    const float* Wm1   = (const float*)d_in[9];
    const float* Wm2   = (const float*)d_in[10];
    const float* Wm3   = (const float*)d_in[11];
    const float* Wm4   = (const float*)d_in[12];
    const float* Wo0a  = (const float*)d_in[13];
    const float* Wo0b  = (const float*)d_in[14];
    const float* Wo1a  = (const float*)d_in[15];
    const float* Wo1b  = (const float*)d_in[16];
    float* out = (float*)d_out;

    // SILU_CST: input-independent — replicate reference quadrature on host (f64).
    double dz = 24.0 / 200000.0;
    double m2 = 0.0;
    const double inv_sqrt2pi = 0.3989422804014326779399460599343818684759;
    for (int i = 0; i <= 200000; i++) {
        double z = -12.0 + i * dz;
        double s = z / (1.0 + exp(-z));
        m2 += s * s * exp(-0.5 * z * z) * inv_sqrt2pi;
    }
    m2 *= dz;
    float silu_cst = (float)(1.0 / sqrt(m2));

    const int SB2 = 2 * C * C * 4;   // 73728 B (two 96x96 buffers)
    const int SB1 = C * C * 4;       // 36864 B
    const int SB3 = 9216 * 4;        // 36864 B

    cudaFuncSetAttribute(k1_kernel,  cudaFuncAttributeMaxDynamicSharedMemorySize, SB2);
    cudaFuncSetAttribute(k2a_kernel, cudaFuncAttributeMaxDynamicSharedMemorySize, SB2);
    cudaFuncSetAttribute(k2b_kernel, cudaFuncAttributeMaxDynamicSharedMemorySize, SB1);
    cudaFuncSetAttribute(k3_kernel,  cudaFuncAttributeMaxDynamicSharedMemorySize, SB3);
    cudaFuncSetAttribute(k4a_kernel, cudaFuncAttributeMaxDynamicSharedMemorySize, SB2);
    cudaFuncSetAttribute(k4b_kernel, cudaFuncAttributeMaxDynamicSharedMemorySize, SB2);

    precompute_kernel<<<36, 256>>>(W00, W11, Wl2_0, bl2_0, Wl2_1);
    k1_kernel<<<GEMM_GRID, GEMM_NT, SB2>>>(nf, pot, Wl1_0, Wl1_1);
    k2a_kernel<<<GEMM_GRID, GEMM_NT, SB2>>>(pot);
    k2b_kernel<<<GEMM_GRID, GEMM_NT, SB1>>>();
    k3_kernel<<<NN / K3_TILE, K3_NT, SB3>>>(Wm1, Wm2, Wm3, Wm4, silu_cst);
    k4a_kernel<<<GEMM_GRID, GEMM_NT, SB2>>>(pot, Wo1a, Wo1b, out);
    k4b_kernel<<<GEMM_GRID, GEMM_NT, SB2>>>(pot, Wo0a, Wo0b, out);
}

// round 6
// speedup vs baseline: 1.0675x; 1.0675x over previous
#include <cuda_runtime.h>
#include <math.h>

#define C 96
#define FOURC 384
#define NN 4096
#define NTH 128          // threads per GEMM CTA
#define NODES_CTA 64     // nodes per GEMM CTA
#define NTILES (NN / NODES_CTA)   // 64

typedef unsigned long long ull;

// ---------------- device scratch (static, no allocations) ----------------
__device__ __align__(16) float g_G0[C * C];
__device__ __align__(16) float g_G1[C * C];
__device__ __align__(16) float g_G2[C * C];
__device__ __align__(16) float g_x0[NN * C];
__device__ __align__(16) float g_x1[3 * NN * C];
__device__ __align__(16) float g_za[NN * C];
__device__ __align__(16) float g_zb[NN * C];
__device__ __align__(16) float g_zc[NN * C];
__device__ __align__(16) float g_tpw[NN * FOURC];
__device__ __align__(16) float g_sa[NN * C];
__device__ __align__(16) float g_sb[3 * NN * C];
__device__ __align__(16) float g_o1[NN * C];
__device__ __align__(16) float g_o2[NN * C];

// ---------------- f32x2 helpers ----------------
__device__ __forceinline__ ull pack2(float a) {
    ull r;
    asm("mov.b64 %0, {%1, %2};" : "=l"(r) : "f"(a), "f"(a));
    return r;
}
__device__ __forceinline__ float2 unpack2(ull v) {
    float2 r;
    asm("mov.b64 {%0, %1}, %2;" : "=f"(r.x), "=f"(r.y) : "l"(v));
    return r;
}
#define FMA2(d, a, b, c) asm("fma.rn.f32x2 %0, %1, %2, %3;" : "=l"(d) : "l"(a), "l"(b), "l"(c))

__device__ __forceinline__ void store12(float* dst, const float v[12])
{
    reinterpret_cast<float4*>(dst)[0] = reinterpret_cast<const float4*>(v)[0];
    reinterpret_cast<float4*>(dst)[1] = reinterpret_cast<const float4*>(v)[1];
    reinterpret_cast<float4*>(dst)[2] = reinterpret_cast<const float4*>(v)[2];
}

// ---------------------------------------------------------------------------
// Precompute: collapse C x C x C fctp tensors against rank-1 y-factors.
// ---------------------------------------------------------------------------
__global__ void precompute_kernel(const float* __restrict__ W00,
                                  const float* __restrict__ W11,
                                  const float* __restrict__ Wl2_0,
                                  const float* __restrict__ bl2_0,
                                  const float* __restrict__ Wl2_1)
{
    int idx = blockIdx.x * 256 + threadIdx.x;
    if (idx >= C * C) return;
    int u = idx / C;
    int w = idx - u * C;
    const float* p00 = W00 + u * C * C + w;
    const float* p11 = W11 + u * C * C + w;
    float a = 0.f, b = 0.f, c = 0.f;
    #pragma unroll 4
    for (int v = 0; v < C; v++) {
        float e00 = p00[v * C];
        float e11 = p11[v * C];
        a = fmaf(Wl2_0[v], e00, a);
        b = fmaf(bl2_0[v], e00, b);
        c = fmaf(Wl2_1[v], e11, c);
    }
    const float inv_s2 = 1.0f / sqrtf(2.0f * C * C);
    const float inv_s3 = 1.0f / sqrtf(3.0f);
    g_G0[idx] = a * inv_s2;
    g_G1[idx] = b * inv_s2;
    g_G2[idx] = c * inv_s2 * inv_s3;
}

// ---------------------------------------------------------------------------
// Shared GEMM machinery: CTA = 64 nodes x 96 cols, K=96.
// Thread tile: 4 nodes x 12 cols (24 f32x2 accumulators).
// smem: Asm (64x96 duplicated f32x2 pairs, 48 KB) then Wsm (96x96 f32, 36 KB).
// ---------------------------------------------------------------------------
#define ASM_BYTES (NODES_CTA * C * 8)          // 49152
#define GEMM_SMEM (ASM_BYTES + C * C * 4)      // 86016

__device__ __forceinline__ void stage_weights(float* Wsm, const float* __restrict__ src)
{
    float4* d = reinterpret_cast<float4*>(Wsm);
    const float4* s = reinterpret_cast<const float4*>(src);
    #pragma unroll
    for (int i = 0; i < (C * C / 4) / NTH; i++)
        d[threadIdx.x + i * NTH] = s[threadIdx.x + i * NTH];
}

__device__ __forceinline__ void gemm_core(const ull* __restrict__ Asm,
                                          const float* __restrict__ Wsm,
                                          int n0, int v0, ull acc[24])
{
    #pragma unroll
    for (int j = 0; j < 24; j++) acc[j] = 0ULL;
    #pragma unroll 4
    for (int k = 0; k < C; k++) {
        const ulonglong2* wr = reinterpret_cast<const ulonglong2*>(Wsm + k * C + v0);
        ulonglong2 wA = wr[0];
        ulonglong2 wB = wr[1];
        ulonglong2 wC = wr[2];
        ull w[6];
        w[0] = wA.x; w[1] = wA.y; w[2] = wB.x; w[3] = wB.y; w[4] = wC.x; w[5] = wC.y;
        ull a[4];
        #pragma unroll
        for (int i = 0; i < 4; i++) a[i] = Asm[(n0 + i) * C + k];
        #pragma unroll
        for (int i = 0; i < 4; i++) {
            #pragma unroll
            for (int j = 0; j < 6; j++)
                FMA2(acc[i * 6 + j], a[i], w[j], acc[i * 6 + j]);
        }
    }
}

__device__ __forceinline__ void gemm_epilogue(float* __restrict__ dstRow0,
                                              int n0, int v0, float scale,
                                              const ull acc[24])
{
    #pragma unroll
    for (int i = 0; i < 4; i++) {
        float o[12];
        #pragma unroll
        for (int j = 0; j < 6; j++) {
            float2 p = unpack2(acc[i * 6 + j]);
            o[2 * j]     = p.x * scale;
            o[2 * j + 1] = p.y * scale;
        }
        store12(dstRow0 + (n0 + i) * C + v0, o);
    }
}

// ---------------------------------------------------------------------------
// P1: y=0: x0 = nf0 @ Wl1_0 * invC ; y=1..3: x1_m = nf1_m @ Wl1_1 * invC
// ---------------------------------------------------------------------------
__global__ void __launch_bounds__(NTH)
p1_kernel(const float* __restrict__ nf,
          const float* __restrict__ Wl1_0, const float* __restrict__ Wl1_1)
{
    extern __shared__ __align__(16) char smraw[];
    ull*   Asm = reinterpret_cast<ull*>(smraw);
    float* Wsm = reinterpret_cast<float*>(smraw + ASM_BYTES);
    const int tid = threadIdx.x;
    const int y   = blockIdx.y;
    const int r0  = blockIdx.x * NODES_CTA;

    stage_weights(Wsm, (y == 0) ? Wl1_0 : Wl1_1);

    if (y == 0) {
        for (int e = tid; e < NODES_CTA * (C / 4); e += NTH) {
            int n = e / (C / 4), kc = (e - n * (C / 4)) * 4;
            float4 v = *reinterpret_cast<const float4*>(nf + (size_t)(r0 + n) * FOURC + kc);
            ull* d = Asm + n * C + kc;
            d[0] = pack2(v.x); d[1] = pack2(v.y); d[2] = pack2(v.z); d[3] = pack2(v.w);
        }
    } else {
        int m = y - 1;
        for (int e = tid; e < NODES_CTA * C; e += NTH) {
            int n = e / C, k = e - n * C;
            Asm[e] = pack2(nf[(size_t)(r0 + n) * FOURC + C + 3 * k + m]);
        }
    }
    __syncthreads();

    const int n0 = (tid >> 3) * 4;
    const int v0 = (tid & 7) * 12;
    ull acc[24];
    gemm_core(Asm, Wsm, n0, v0, acc);

    const float INVC = 1.0f / sqrtf((float)C);
    float* dst = (y == 0) ? g_x0 : (g_x1 + (size_t)(y - 1) * NN * C);
    gemm_epilogue(dst + (size_t)r0 * C, n0, v0, INVC, acc);
}

// ---------------------------------------------------------------------------
// P2: y=0: za = (p0*x0) @ G0 ; y=1: zb = x0 @ G1 ; y=2: zc = q @ G2
//     (q recomputed elementwise from x1 and pot)
// ---------------------------------------------------------------------------
__global__ void __launch_bounds__(NTH)
p2_kernel(const float* __restrict__ pot)
{
    extern __shared__ __align__(16) char smraw[];
    ull*   Asm = reinterpret_cast<ull*>(smraw);
    float* Wsm = reinterpret_cast<float*>(smraw + ASM_BYTES);
    const int tid = threadIdx.x;
    const int y   = blockIdx.y;
    const int r0  = blockIdx.x * NODES_CTA;

    stage_weights(Wsm, (y == 0) ? g_G0 : (y == 1) ? g_G1 : g_G2);

    for (int e = tid; e < NODES_CTA * C; e += NTH) {
        int n = e / C, k = e - n * C;
        size_t gi = (size_t)(r0 + n) * C + k;
        float a;
        if (y == 0)      a = pot[(r0 + n) * 4] * g_x0[gi];
        else if (y == 1) a = g_x0[gi];
        else {
            a = g_x1[gi] * pot[(r0 + n) * 4 + 1]
              + g_x1[(size_t)NN * C + gi] * pot[(r0 + n) * 4 + 2]
              + g_x1[2 * (size_t)NN * C + gi] * pot[(r0 + n) * 4 + 3];
        }
        Asm[e] = pack2(a);
    }
    __syncthreads();

    const int n0 = (tid >> 3) * 4;
    const int v0 = (tid & 7) * 12;
    ull acc[24];
    gemm_core(Asm, Wsm, n0, v0, acc);

    float* dst = (y == 0) ? g_za : (y == 1) ? g_zb : g_zc;
    gemm_epilogue(dst + (size_t)r0 * C, n0, v0, 1.0f, acc);
}

// ---------------------------------------------------------------------------
// P3: MLP  norms=(za+zb+zc)^2 -> tp_w   (TILE 32 nodes, 256 threads)
// ---------------------------------------------------------------------------
#define K3_TILE 32
#define K3_NT   256
#define K3_SMEM ((1536 + 256 + 256 + 6144 + 3072 + 512 + 512) * 4)
__global__ void __launch_bounds__(K3_NT)
p3_kernel(const float* __restrict__ Wm1, const float* __restrict__ Wm2,
          const float* __restrict__ Wm3, const float* __restrict__ Wm4,
          float silu_cst)
{
    extern __shared__ __align__(16) float sm[];
    float* W1 = sm;            // 96x16
    float* W2 = sm + 1536;     // 16x16
    float* W3 = sm + 1792;     // 16x16
    float* W4 = sm + 2048;     // 16x384
    float* NR = sm + 8192;     // 32x96
    float* H1 = sm + 11264;    // 32x16
    float* H2 = sm + 11776;    // 32x16
    const int tid  = threadIdx.x;
    const int base = blockIdx.x * K3_TILE;
    const float INVC = 1.0f / sqrtf((float)C);
    const float cst = silu_cst;

    {
        float4* d; const float4* s;
        d = (float4*)W1; s = (const float4*)Wm1;
        for (int i = tid; i < 1536 / 4; i += K3_NT) d[i] = s[i];
        d = (float4*)W2; s = (const float4*)Wm2;
        for (int i = tid; i < 256 / 4; i += K3_NT) d[i] = s[i];
        d = (float4*)W3; s = (const float4*)Wm3;
        for (int i = tid; i < 256 / 4; i += K3_NT) d[i] = s[i];
        d = (float4*)W4; s = (const float4*)Wm4;
        for (int i = tid; i < 6144 / 4; i += K3_NT) d[i] = s[i];
    }
    for (int e = tid; e < K3_TILE * C; e += K3_NT) {
        int n = e / C, k = e - n * C;
        size_t gi = (size_t)(base + n) * C + k;
        float v = g_za[gi] + g_zb[gi] + g_zc[gi];
        NR[e] = v * v;
    }
    __syncthreads();

    #pragma unroll
    for (int idx = tid; idx < K3_TILE * 16; idx += K3_NT) {
        int nn = idx >> 4, j = idx & 15;
        const float* nr = NR + nn * C;
        float s = 0.f;
        #pragma unroll 8
        for (int u = 0; u < C; u++) s = fmaf(nr[u], W1[u * 16 + j], s);
        s *= INVC;
        H1[idx] = cst * s / (1.0f + expf(-s));
    }
    __syncthreads();
    #pragma unroll
    for (int idx = tid; idx < K3_TILE * 16; idx += K3_NT) {
        int nn = idx >> 4, j = idx & 15;
        float s = 0.f;
        #pragma unroll
        for (int k = 0; k < 16; k++) s = fmaf(H1[nn * 16 + k], W2[k * 16 + j], s);
        s *= 0.25f;
        H2[idx] = cst * s / (1.0f + expf(-s));
    }
    __syncthreads();
    #pragma unroll
    for (int idx = tid; idx < K3_TILE * 16; idx += K3_NT) {
        int nn = idx >> 4, j = idx & 15;
        float s = 0.f;
        #pragma unroll
        for (int k = 0; k < 16; k++) s = fmaf(H2[nn * 16 + k], W3[k * 16 + j], s);
        s *= 0.25f;
        H1[idx] = cst * s / (1.0f + expf(-s));
    }
    __syncthreads();
    for (int idx = tid; idx < K3_TILE * FOURC; idx += K3_NT) {
        int nn = idx / FOURC, j = idx - nn * FOURC;
        float s = 0.f;
        #pragma unroll
        for (int k = 0; k < 16; k++) s = fmaf(H1[nn * 16 + k], W4[k * FOURC + j], s);
        g_tpw[(size_t)(base + nn) * FOURC + j] = s * 0.25f;
    }
}

// ---------------------------------------------------------------------------
// P4: y=0: sa = (w01*x0) @ Wo1a ; y=1..3: sb_m = (w10*x1_m) @ Wo1b
// ---------------------------------------------------------------------------
__global__ void __launch_bounds__(NTH)
p4_kernel(const float* __restrict__ Wo1a, const float* __restrict__ Wo1b)
{
    extern __shared__ __align__(16) char smraw[];
    ull*   Asm = reinterpret_cast<ull*>(smraw);
    float* Wsm = reinterpret_cast<float*>(smraw + ASM_BYTES);
    const int tid = threadIdx.x;
    const int y   = blockIdx.y;
    const int r0  = blockIdx.x * NODES_CTA;

    stage_weights(Wsm, (y == 0) ? Wo1a : Wo1b);

    for (int e = tid; e < NODES_CTA * C; e += NTH) {
        int n = e / C, k = e - n * C;
        size_t gi = (size_t)(r0 + n) * C + k;
        size_t ti = (size_t)(r0 + n) * FOURC;
        float a;
        if (y == 0) a = g_tpw[ti + C + k] * g_x0[gi];
        else        a = g_tpw[ti + 2 * C + k] * g_x1[(size_t)(y - 1) * NN * C + gi];
        Asm[e] = pack2(a);
    }
    __syncthreads();

    const int n0 = (tid >> 3) * 4;
    const int v0 = (tid & 7) * 12;
    ull acc[24];
    gemm_core(Asm, Wsm, n0, v0, acc);

    float* dst = (y == 0) ? g_sa : (g_sb + (size_t)(y - 1) * NN * C);
    gemm_epilogue(dst + (size_t)r0 * C, n0, v0, 1.0f, acc);
}

// ---------------------------------------------------------------------------
// P5: y=0: o1 = (w00*x0) @ Wo0a ; y=1: o2 = (w11*q) @ Wo0b
// ---------------------------------------------------------------------------
__global__ void __launch_bounds__(NTH)
p5_kernel(const float* __restrict__ pot,
          const float* __restrict__ Wo0a, const float* __restrict__ Wo0b)
{
    extern __shared__ __align__(16) char smraw[];
    ull*   Asm = reinterpret_cast<ull*>(smraw);
    float* Wsm = reinterpret_cast<float*>(smraw + ASM_BYTES);
    const int tid = threadIdx.x;
    const int y   = blockIdx.y;
    const int r0  = blockIdx.x * NODES_CTA;

    stage_weights(Wsm, (y == 0) ? Wo0a : Wo0b);

    for (int e = tid; e < NODES_CTA * C; e += NTH) {
        int n = e / C, k = e - n * C;
        size_t gi = (size_t)(r0 + n) * C + k;
        size_t ti = (size_t)(r0 + n) * FOURC;
        float a;
        if (y == 0) a = g_tpw[ti + k] * g_x0[gi];
        else {
            float q = g_x1[gi] * pot[(r0 + n) * 4 + 1]
                    + g_x1[(size_t)NN * C + gi] * pot[(r0 + n) * 4 + 2]
                    + g_x1[2 * (size_t)NN * C + gi] * pot[(r0 + n) * 4 + 3];
            a = g_tpw[ti + 3 * C + k] * q;
        }
        Asm[e] = pack2(a);
    }
    __syncthreads();

    const int n0 = (tid >> 3) * 4;
    const int v0 = (tid & 7) * 12;
    ull acc[24];
    gemm_core(Asm, Wsm, n0, v0, acc);

    float* dst = (y == 0) ? g_o1 : g_o2;
    gemm_epilogue(dst + (size_t)r0 * C, n0, v0, 1.0f, acc);
}

// ---------------------------------------------------------------------------
// P6: final combiner
// out0 = (p0*o1 + o2/sqrt3) * norm_out
// out1[v,m] = (p1m*sa[v] + p0*sb_m[v]) * norm_out
// ---------------------------------------------------------------------------
__global__ void __launch_bounds__(NTH)
p6_kernel(const float* __restrict__ pot, float* __restrict__ out)
{
    const int t   = blockIdx.x * NTH + threadIdx.x;
    const int row = t >> 3;
    const int v0  = (t & 7) * 12;
    const float NORM_OUT  = 1.0f / sqrtf(2.0f * C);
    const float INV_SQRT3 = 1.0f / sqrtf(3.0f);

    const float p0 = pot[row * 4 + 0];
    const float p1 = pot[row * 4 + 1];
    const float p2 = pot[row * 4 + 2];
    const float p3 = pot[row * 4 + 3];

    const size_t gi = (size_t)row * C + v0;
    float sa[12], sb0[12], sb1[12], sb2[12], o1[12], o2[12];
    #pragma unroll
    for (int i = 0; i < 3; i++) {
        reinterpret_cast<float4*>(sa)[i]  = reinterpret_cast<const float4*>(g_sa + gi)[i];
        reinterpret_cast<float4*>(sb0)[i] = reinterpret_cast<const float4*>(g_sb + gi)[i];
        reinterpret_cast<float4*>(sb1)[i] = reinterpret_cast<const float4*>(g_sb + (size_t)NN * C + gi)[i];
        reinterpret_cast<float4*>(sb2)[i] = reinterpret_cast<const float4*>(g_sb + 2 * (size_t)NN * C + gi)[i];
        reinterpret_cast<float4*>(o1)[i]  = reinterpret_cast<const float4*>(g_o1 + gi)[i];
        reinterpret_cast<float4*>(o2)[i]  = reinterpret_cast<const float4*>(g_o2 + gi)[i];
    }

    float a[12];
    #pragma unroll
    for (int j = 0; j < 12; j++)
        a[j] = (p0 * o1[j] + o2[j] * INV_SQRT3) * NORM_OUT;
    store12(out + (size_t)row * FOURC + v0, a);

    float b[36];
    #pragma unroll
    for (int j = 0; j < 12; j++) {
        float s = sa[j];
        b[j * 3 + 0] = (p1 * s + p0 * sb0[j]) * NORM_OUT;
        b[j * 3 + 1] = (p2 * s + p0 * sb1[j]) * NORM_OUT;
        b[j * 3 + 2] = (p3 * s + p0 * sb2[j]) * NORM_OUT;
    }
    float4* dst = reinterpret_cast<float4*>(out + (size_t)row * FOURC + C + v0 * 3);
    #pragma unroll
    for (int i = 0; i < 9; i++) dst[i] = reinterpret_cast<const float4*>(b)[i];
}

// ---------------------------------------------------------------------------
extern "C" void kernel_launch(void* const* d_in, const int* in_sizes, int n_in,
                              void* d_out, int out_size)
{
    const float* nf    = (const float*)d_in[0];
    const float* pot   = (const float*)d_in[1];
    const float* Wl1_0 = (const float*)d_in[2];
    const float* Wl1_1 = (const float*)d_in[3];
    const float* Wl2_0 = (const float*)d_in[4];
    const float* bl2_0 = (const float*)d_in[5];
    const float* Wl2_1 = (const float*)d_in[6];
    const float* W00   = (const float*)d_in[7];
    const float* W11   = (const float*)d_in[8];
    const float* Wm1   = (const float*)d_in[9];
    const float* Wm2   = (const float*)d_in[10];
    const float* Wm3   = (const float*)d_in[11];
    const float* Wm4   = (const float*)d_in[12];
    const float* Wo0a  = (const float*)d_in[13];
    const float* Wo0b  = (const float*)d_in[14];
    const float* Wo1a  = (const float*)d_in[15];
    const float* Wo1b  = (const float*)d_in[16];
    float* out = (float*)d_out;

    // SILU_CST: input-independent — replicate reference quadrature on host (f64).
    double dz = 24.0 / 200000.0;
    double m2 = 0.0;
    const double inv_sqrt2pi = 0.3989422804014326779399460599343818684759;
    for (int i = 0; i <= 200000; i++) {
        double z = -12.0 + i * dz;
        double s = z / (1.0 + exp(-z));
        m2 += s * s * exp(-0.5 * z * z) * inv_sqrt2pi;
    }
    m2 *= dz;
    float silu_cst = (float)(1.0 / sqrt(m2));

    cudaFuncSetAttribute(p1_kernel, cudaFuncAttributeMaxDynamicSharedMemorySize, GEMM_SMEM);
    cudaFuncSetAttribute(p2_kernel, cudaFuncAttributeMaxDynamicSharedMemorySize, GEMM_SMEM);
    cudaFuncSetAttribute(p3_kernel, cudaFuncAttributeMaxDynamicSharedMemorySize, K3_SMEM);
    cudaFuncSetAttribute(p4_kernel, cudaFuncAttributeMaxDynamicSharedMemorySize, GEMM_SMEM);
    cudaFuncSetAttribute(p5_kernel, cudaFuncAttributeMaxDynamicSharedMemorySize, GEMM_SMEM);

    precompute_kernel<<<36, 256>>>(W00, W11, Wl2_0, bl2_0, Wl2_1);
    p1_kernel<<<dim3(NTILES, 4), NTH, GEMM_SMEM>>>(nf, Wl1_0, Wl1_1);
    p2_kernel<<<dim3(NTILES, 3), NTH, GEMM_SMEM>>>(pot);
    p3_kernel<<<NN / K3_TILE, K3_NT, K3_SMEM>>>(Wm1, Wm2, Wm3, Wm4, silu_cst);
    p4_kernel<<<dim3(NTILES, 4), NTH, GEMM_SMEM>>>(Wo1a, Wo1b);
    p5_kernel<<<dim3(NTILES, 2), NTH, GEMM_SMEM>>>(pot, Wo0a, Wo0b);
    p6_kernel<<<NN * 8 / NTH, NTH>>>(pot, out);
}

// round 7
// speedup vs baseline: 1.3692x; 1.2826x over previous
#include <cuda_runtime.h>
#include <math.h>

#define C 96
#define FOURC 384
#define NN 4096
#define TILE 32
#define NTH 128
#define NCTAS (NN / TILE)   // 128

typedef unsigned long long ull;

// padded strides (floats) to avoid 4-way LDS bank conflicts across node-groups
#define XS 97               // node arrays with C cols
#define GS 385              // tp_w rows
#define X1P (TILE * XS)     // x1 plane stride

// ---------------- shared memory layout (floats) ----------------
#define OFF_B    0          // 9216 : weight buffer A (96x96)
#define OFF_B2   9216       // 9216 : weight buffer B / MLP weights
#define OFF_X0   18432      // 32*97 = 3104
#define OFF_X1   21536      // 3*3104 = 9312
#define OFF_Q    30848      // 3104
#define OFF_F    33952      // 3104 (norms)
#define OFF_G    37056      // 32*385 = 12320 (tp_w)
#define OFF_H1   49376      // 512
#define OFF_H2   49888      // 512
#define OFF_POT  50400      // 128
#define SMEM_FLOATS 50528
#define SMEM_BYTES (SMEM_FLOATS * 4)   // 202112 B -> 1 CTA/SM

// ---------------- device scratch ----------------
__device__ __align__(16) float g_G0[C * C];
__device__ __align__(16) float g_G1[C * C];
__device__ __align__(16) float g_G2[C * C];

// ---------------- f32x2 helpers ----------------
__device__ __forceinline__ ull dup2(float a) {
    ull r;
    asm("mov.b64 %0, {%1, %1};" : "=l"(r) : "f"(a));
    return r;
}
__device__ __forceinline__ float2 unp2(ull v) {
    float2 r;
    asm("mov.b64 {%0, %1}, %2;" : "=f"(r.x), "=f"(r.y) : "l"(v));
    return r;
}
#define FMA2(d, a, b, cc) asm("fma.rn.f32x2 %0, %1, %2, %3;" : "=l"(d) : "l"(a), "l"(b), "l"(cc))

// NS activation streams x 12 cols against one 12-col weight row slice.
template<int NS>
__device__ __forceinline__ void fma2_ns(ull* acc, const ull* pv, const float* wrow)
{
    ulonglong2 wa = *reinterpret_cast<const ulonglong2*>(wrow);
    ulonglong2 wb = *reinterpret_cast<const ulonglong2*>(wrow + 4);
    ulonglong2 wc = *reinterpret_cast<const ulonglong2*>(wrow + 8);
    ull w0 = wa.x, w1 = wa.y, w2 = wb.x, w3 = wb.y, w4 = wc.x, w5 = wc.y;
    #pragma unroll
    for (int s = 0; s < NS; s++) {
        FMA2(acc[s*6+0], pv[s], w0, acc[s*6+0]);
        FMA2(acc[s*6+1], pv[s], w1, acc[s*6+1]);
        FMA2(acc[s*6+2], pv[s], w2, acc[s*6+2]);
        FMA2(acc[s*6+3], pv[s], w3, acc[s*6+3]);
        FMA2(acc[s*6+4], pv[s], w4, acc[s*6+4]);
        FMA2(acc[s*6+5], pv[s], w5, acc[s*6+5]);
    }
}

__device__ __forceinline__ void unp12(float o[12], const ull a[6])
{
    #pragma unroll
    for (int j = 0; j < 6; j++) {
        float2 p = unp2(a[j]);
        o[2*j] = p.x; o[2*j+1] = p.y;
    }
}

// ---------------------------------------------------------------------------
// Precompute: collapse C x C x C fctp tensors against rank-1 y-factors.
// ---------------------------------------------------------------------------
__global__ void precompute_kernel(const float* __restrict__ W00,
                                  const float* __restrict__ W11,
                                  const float* __restrict__ Wl2_0,
                                  const float* __restrict__ bl2_0,
                                  const float* __restrict__ Wl2_1)
{
    int idx = blockIdx.x * 256 + threadIdx.x;
    if (idx >= C * C) return;
    int u = idx / C;
    int w = idx - u * C;
    const float* p00 = W00 + u * C * C + w;
    const float* p11 = W11 + u * C * C + w;
    float a = 0.f, b = 0.f, c = 0.f;
    #pragma unroll 4
    for (int v = 0; v < C; v++) {
        float e00 = p00[v * C];
        float e11 = p11[v * C];
        a = fmaf(Wl2_0[v], e00, a);
        b = fmaf(bl2_0[v], e00, b);
        c = fmaf(Wl2_1[v], e11, c);
    }
    const float inv_s2 = 1.0f / sqrtf(2.0f * C * C);
    const float inv_s3 = 1.0f / sqrtf(3.0f);
    g_G0[idx] = a * inv_s2;
    g_G1[idx] = b * inv_s2;
    g_G2[idx] = c * inv_s2 * inv_s3;
}

__device__ __forceinline__ void stageW4(float* dst, const float* __restrict__ src, int n4)
{
    float4* d = reinterpret_cast<float4*>(dst);
    const float4* s = reinterpret_cast<const float4*>(src);
    for (int i = threadIdx.x; i < n4; i += NTH) d[i] = s[i];
}

// ---------------------------------------------------------------------------
// Fused main kernel: 1 CTA = 32 nodes; thread owns 2 nodes {g, g+16} x 12 cols.
// ---------------------------------------------------------------------------
__global__ void __launch_bounds__(NTH, 1)
main_kernel(const float* __restrict__ nf, const float* __restrict__ pot,
            const float* __restrict__ Wl1_0, const float* __restrict__ Wl1_1,
            const float* __restrict__ Wm1, const float* __restrict__ Wm2,
            const float* __restrict__ Wm3, const float* __restrict__ Wm4,
            const float* __restrict__ Wo0a, const float* __restrict__ Wo0b,
            const float* __restrict__ Wo1a, const float* __restrict__ Wo1b,
            float* __restrict__ out, float silu_cst)
{
    extern __shared__ __align__(16) float sm[];
    float* B   = sm + OFF_B;
    float* B2  = sm + OFF_B2;
    float* X0  = sm + OFF_X0;
    float* X1  = sm + OFF_X1;
    float* Q   = sm + OFF_Q;
    float* F   = sm + OFF_F;
    float* G   = sm + OFF_G;
    float* H1  = sm + OFF_H1;
    float* H2  = sm + OFF_H2;
    float* POT = sm + OFF_POT;

    const float INVC      = 1.0f / sqrtf((float)C);
    const float INV_SQRT3 = 1.0f / sqrtf(3.0f);
    const float NORM_OUT  = 1.0f / sqrtf(2.0f * C);

    const int tid  = threadIdx.x;
    const int base = blockIdx.x * TILE;
    const int g    = tid >> 3;          // 0..15
    const int na   = g, nb = g + 16;
    const int v0   = (tid & 7) * 12;
    const int rowa = base + na;
    const int rowb = base + nb;

    // ---- S1: pot + Wl1_0 + Wl1_1 ----
    POT[tid] = pot[base * 4 + tid];
    stageW4(B,  Wl1_0, C * C / 4);
    stageW4(B2, Wl1_1, C * C / 4);
    __syncthreads();

    // ---- C1: x0 = nf0 @ Wl1_0 * invC (A from gmem) ----
    {
        ull acc[12];
        #pragma unroll
        for (int j = 0; j < 12; j++) acc[j] = 0ULL;
        const float* ra = nf + (size_t)rowa * FOURC;
        const float* rb = nf + (size_t)rowb * FOURC;
        for (int u = 0; u < C; u += 4) {
            float4 a4 = *reinterpret_cast<const float4*>(ra + u);
            float4 b4 = *reinterpret_cast<const float4*>(rb + u);
            ull pv[2];
            pv[0] = dup2(a4.x); pv[1] = dup2(b4.x);
            fma2_ns<2>(acc, pv, B + (u + 0) * C + v0);
            pv[0] = dup2(a4.y); pv[1] = dup2(b4.y);
            fma2_ns<2>(acc, pv, B + (u + 1) * C + v0);
            pv[0] = dup2(a4.z); pv[1] = dup2(b4.z);
            fma2_ns<2>(acc, pv, B + (u + 2) * C + v0);
            pv[0] = dup2(a4.w); pv[1] = dup2(b4.w);
            fma2_ns<2>(acc, pv, B + (u + 3) * C + v0);
        }
        float oa[12], ob[12];
        unp12(oa, acc); unp12(ob, acc + 6);
        #pragma unroll
        for (int j = 0; j < 12; j++) {
            X0[na * XS + v0 + j] = oa[j] * INVC;
            X0[nb * XS + v0 + j] = ob[j] * INVC;
        }
    }

    // ---- C2: x1_m = nf1_m @ Wl1_1 * invC (6 streams) ; q = sum_m x1_m p1_m ----
    {
        ull acc[36];
        #pragma unroll
        for (int j = 0; j < 36; j++) acc[j] = 0ULL;
        const float* ra = nf + (size_t)rowa * FOURC + C;
        const float* rb = nf + (size_t)rowb * FOURC + C;
        for (int u = 0; u < C; u += 4) {
            float4 a0 = *reinterpret_cast<const float4*>(ra + u * 3);
            float4 a1 = *reinterpret_cast<const float4*>(ra + u * 3 + 4);
            float4 a2 = *reinterpret_cast<const float4*>(ra + u * 3 + 8);
            float4 b0 = *reinterpret_cast<const float4*>(rb + u * 3);
            float4 b1 = *reinterpret_cast<const float4*>(rb + u * 3 + 4);
            float4 b2 = *reinterpret_cast<const float4*>(rb + u * 3 + 8);
            ull pv[6];
            pv[0]=dup2(a0.x); pv[1]=dup2(a0.y); pv[2]=dup2(a0.z);
            pv[3]=dup2(b0.x); pv[4]=dup2(b0.y); pv[5]=dup2(b0.z);
            fma2_ns<6>(acc, pv, B2 + (u + 0) * C + v0);
            pv[0]=dup2(a0.w); pv[1]=dup2(a1.x); pv[2]=dup2(a1.y);
            pv[3]=dup2(b0.w); pv[4]=dup2(b1.x); pv[5]=dup2(b1.y);
            fma2_ns<6>(acc, pv, B2 + (u + 1) * C + v0);
            pv[0]=dup2(a1.z); pv[1]=dup2(a1.w); pv[2]=dup2(a2.x);
            pv[3]=dup2(b1.z); pv[4]=dup2(b1.w); pv[5]=dup2(b2.x);
            fma2_ns<6>(acc, pv, B2 + (u + 2) * C + v0);
            pv[0]=dup2(a2.y); pv[1]=dup2(a2.z); pv[2]=dup2(a2.w);
            pv[3]=dup2(b2.y); pv[4]=dup2(b2.z); pv[5]=dup2(b2.w);
            fma2_ns<6>(acc, pv, B2 + (u + 3) * C + v0);
        }
        float pa1 = POT[na*4+1], pa2 = POT[na*4+2], pa3 = POT[na*4+3];
        float pb1 = POT[nb*4+1], pb2 = POT[nb*4+2], pb3 = POT[nb*4+3];
        float e[6][12];
        #pragma unroll
        for (int s = 0; s < 6; s++) unp12(e[s], acc + s * 6);
        #pragma unroll
        for (int j = 0; j < 12; j++) {
            float a0 = e[0][j]*INVC, a1 = e[1][j]*INVC, a2 = e[2][j]*INVC;
            float b0 = e[3][j]*INVC, b1 = e[4][j]*INVC, b2 = e[5][j]*INVC;
            X1[0*X1P + na*XS + v0 + j] = a0;
            X1[1*X1P + na*XS + v0 + j] = a1;
            X1[2*X1P + na*XS + v0 + j] = a2;
            X1[0*X1P + nb*XS + v0 + j] = b0;
            X1[1*X1P + nb*XS + v0 + j] = b1;
            X1[2*X1P + nb*XS + v0 + j] = b2;
            Q[na*XS + v0 + j] = a0*pa1 + a1*pa2 + a2*pa3;
            Q[nb*XS + v0 + j] = b0*pb1 + b1*pb2 + b2*pb3;
        }
    }
    __syncthreads();

    // ---- S2: G0 + G1 ----
    stageW4(B,  g_G0, C * C / 4);
    stageW4(B2, g_G1, C * C / 4);
    __syncthreads();

    // ---- C3: s0 = x0@G0, s1 = x0@G1 ; z = p0*s0 + s1 ----
    float zfa[12], zfb[12];
    {
        ull accA[12], accB[12];
        #pragma unroll
        for (int j = 0; j < 12; j++) { accA[j] = 0ULL; accB[j] = 0ULL; }
        #pragma unroll 4
        for (int k = 0; k < C; k++) {
            ull pv[2];
            pv[0] = dup2(X0[na * XS + k]);
            pv[1] = dup2(X0[nb * XS + k]);
            fma2_ns<2>(accA, pv, B  + k * C + v0);
            fma2_ns<2>(accB, pv, B2 + k * C + v0);
        }
        float sa0[12], sb0[12], sa1[12], sb1[12];
        unp12(sa0, accA); unp12(sb0, accA + 6);
        unp12(sa1, accB); unp12(sb1, accB + 6);
        float p0a = POT[na*4], p0b = POT[nb*4];
        #pragma unroll
        for (int j = 0; j < 12; j++) {
            zfa[j] = p0a * sa0[j] + sa1[j];
            zfb[j] = p0b * sb0[j] + sb1[j];
        }
    }
    __syncthreads();

    // ---- S3: G2 -> B, MLP weights -> B2 ----
    stageW4(B, g_G2, C * C / 4);
    stageW4(B2,        Wm1, (C * 16) / 4);
    stageW4(B2 + 1536, Wm2, (16 * 16) / 4);
    stageW4(B2 + 1792, Wm3, (16 * 16) / 4);
    stageW4(B2 + 2048, Wm4, (16 * FOURC) / 4);
    __syncthreads();

    // ---- C4: z += q@G2 ; F = z^2 ----
    {
        ull acc[12];
        #pragma unroll
        for (int j = 0; j < 12; j++) acc[j] = 0ULL;
        #pragma unroll 4
        for (int k = 0; k < C; k++) {
            ull pv[2];
            pv[0] = dup2(Q[na * XS + k]);
            pv[1] = dup2(Q[nb * XS + k]);
            fma2_ns<2>(acc, pv, B + k * C + v0);
        }
        float ta[12], tb[12];
        unp12(ta, acc); unp12(tb, acc + 6);
        #pragma unroll
        for (int j = 0; j < 12; j++) {
            float pa = zfa[j] + ta[j];
            float pb = zfb[j] + tb[j];
            F[na * XS + v0 + j] = pa * pa;
            F[nb * XS + v0 + j] = pb * pb;
        }
    }
    __syncthreads();

    // ---- C5: MLP F -> tp_w (G) ----
    {
        const float cst = silu_cst;
        #pragma unroll
        for (int idx = tid; idx < TILE * 16; idx += NTH) {
            int nn = idx >> 4, j = idx & 15;
            const float* nr = F + nn * XS;
            float s = 0.f;
            #pragma unroll 8
            for (int u = 0; u < C; u++) s = fmaf(nr[u], B2[u * 16 + j], s);
            s *= INVC;
            H1[idx] = cst * s / (1.0f + expf(-s));
        }
        __syncthreads();
        #pragma unroll
        for (int idx = tid; idx < TILE * 16; idx += NTH) {
            int nn = idx >> 4, j = idx & 15;
            float s = 0.f;
            #pragma unroll
            for (int k = 0; k < 16; k++) s = fmaf(H1[nn * 16 + k], B2[1536 + k * 16 + j], s);
            s *= 0.25f;
            H2[idx] = cst * s / (1.0f + expf(-s));
        }
        __syncthreads();
        #pragma unroll
        for (int idx = tid; idx < TILE * 16; idx += NTH) {
            int nn = idx >> 4, j = idx & 15;
            float s = 0.f;
            #pragma unroll
            for (int k = 0; k < 16; k++) s = fmaf(H2[nn * 16 + k], B2[1792 + k * 16 + j], s);
            s *= 0.25f;
            H1[idx] = cst * s / (1.0f + expf(-s));
        }
        __syncthreads();
        for (int nn = 0; nn < TILE; nn++) {
            float h[16];
            #pragma unroll
            for (int k = 0; k < 16; k++) h[k] = H1[nn * 16 + k];
            #pragma unroll
            for (int jj = 0; jj < 3; jj++) {
                int j = tid + jj * NTH;
                float s = 0.f;
                #pragma unroll
                for (int k = 0; k < 16; k++) s = fmaf(h[k], B2[2048 + k * FOURC + j], s);
                G[nn * GS + j] = s * 0.25f;
            }
        }
    }
    __syncthreads();

    // ---- S4: Wo1a + Wo1b ----
    stageW4(B,  Wo1a, C * C / 4);
    stageW4(B2, Wo1b, C * C / 4);
    __syncthreads();

    const float p0a = POT[na*4],   p0b = POT[nb*4];
    const float pa1 = POT[na*4+1], pa2 = POT[na*4+2], pa3 = POT[na*4+3];
    const float pb1 = POT[nb*4+1], pb2 = POT[nb*4+2], pb3 = POT[nb*4+3];

    // ---- C6: sa = (w01*x0) @ Wo1a (regs) ----
    float safa[12], safb[12];
    {
        ull acc[12];
        #pragma unroll
        for (int j = 0; j < 12; j++) acc[j] = 0ULL;
        #pragma unroll 4
        for (int k = 0; k < C; k++) {
            ull pv[2];
            pv[0] = dup2(G[na * GS + C + k] * X0[na * XS + k]);
            pv[1] = dup2(G[nb * GS + C + k] * X0[nb * XS + k]);
            fma2_ns<2>(acc, pv, B + k * C + v0);
        }
        unp12(safa, acc); unp12(safb, acc + 6);
    }

    // ---- C7: sb_m = (w10*x1_m) @ Wo1b (6 streams) ; write out1 ----
    {
        ull acc[36];
        #pragma unroll
        for (int j = 0; j < 36; j++) acc[j] = 0ULL;
        #pragma unroll 2
        for (int k = 0; k < C; k++) {
            float wa = G[na * GS + 2 * C + k];
            float wb = G[nb * GS + 2 * C + k];
            ull pv[6];
            pv[0] = dup2(wa * X1[0*X1P + na*XS + k]);
            pv[1] = dup2(wa * X1[1*X1P + na*XS + k]);
            pv[2] = dup2(wa * X1[2*X1P + na*XS + k]);
            pv[3] = dup2(wb * X1[0*X1P + nb*XS + k]);
            pv[4] = dup2(wb * X1[1*X1P + nb*XS + k]);
            pv[5] = dup2(wb * X1[2*X1P + nb*XS + k]);
            fma2_ns<6>(acc, pv, B2 + k * C + v0);
        }
        float e[6][12];
        #pragma unroll
        for (int s = 0; s < 6; s++) unp12(e[s], acc + s * 6);
        float oa[36], ob[36];
        #pragma unroll
        for (int j = 0; j < 12; j++) {
            float sA = safa[j], sB = safb[j];
            oa[j*3+0] = (pa1 * sA + p0a * e[0][j]) * NORM_OUT;
            oa[j*3+1] = (pa2 * sA + p0a * e[1][j]) * NORM_OUT;
            oa[j*3+2] = (pa3 * sA + p0a * e[2][j]) * NORM_OUT;
            ob[j*3+0] = (pb1 * sB + p0b * e[3][j]) * NORM_OUT;
            ob[j*3+1] = (pb2 * sB + p0b * e[4][j]) * NORM_OUT;
            ob[j*3+2] = (pb3 * sB + p0b * e[5][j]) * NORM_OUT;
        }
        float4* da = reinterpret_cast<float4*>(out + (size_t)rowa * FOURC + C + v0 * 3);
        float4* db = reinterpret_cast<float4*>(out + (size_t)rowb * FOURC + C + v0 * 3);
        #pragma unroll
        for (int i = 0; i < 9; i++) {
            da[i] = reinterpret_cast<const float4*>(oa)[i];
            db[i] = reinterpret_cast<const float4*>(ob)[i];
        }
    }
    __syncthreads();

    // ---- S5: Wo0a + Wo0b ----
    stageW4(B,  Wo0a, C * C / 4);
    stageW4(B2, Wo0b, C * C / 4);
    __syncthreads();

    // ---- C8: out0 = (p0*((w00*x0)@Wo0a) + inv3*((w11*q)@Wo0b)) * norm ----
    {
        ull acc1[12], acc2[12];
        #pragma unroll
        for (int j = 0; j < 12; j++) { acc1[j] = 0ULL; acc2[j] = 0ULL; }
        #pragma unroll 2
        for (int k = 0; k < C; k++) {
            ull pv[2];
            pv[0] = dup2(G[na * GS + k] * X0[na * XS + k]);
            pv[1] = dup2(G[nb * GS + k] * X0[nb * XS + k]);
            fma2_ns<2>(acc1, pv, B + k * C + v0);
            pv[0] = dup2(G[na * GS + 3 * C + k] * Q[na * XS + k]);
            pv[1] = dup2(G[nb * GS + 3 * C + k] * Q[nb * XS + k]);
            fma2_ns<2>(acc2, pv, B2 + k * C + v0);
        }
        float o1a[12], o1b[12], o2a[12], o2b[12];
        unp12(o1a, acc1); unp12(o1b, acc1 + 6);
        unp12(o2a, acc2); unp12(o2b, acc2 + 6);
        float oa[12], ob[12];
        #pragma unroll
        for (int j = 0; j < 12; j++) {
            oa[j] = (p0a * o1a[j] + o2a[j] * INV_SQRT3) * NORM_OUT;
            ob[j] = (p0b * o1b[j] + o2b[j] * INV_SQRT3) * NORM_OUT;
        }
        float4* da = reinterpret_cast<float4*>(out + (size_t)rowa * FOURC + v0);
        float4* db = reinterpret_cast<float4*>(out + (size_t)rowb * FOURC + v0);
        #pragma unroll
        for (int i = 0; i < 3; i++) {
            da[i] = reinterpret_cast<const float4*>(oa)[i];
            db[i] = reinterpret_cast<const float4*>(ob)[i];
        }
    }
}

// ---------------------------------------------------------------------------
extern "C" void kernel_launch(void* const* d_in, const int* in_sizes, int n_in,
                              void* d_out, int out_size)
{
    const float* nf    = (const float*)d_in[0];
    const float* pot   = (const float*)d_in[1];
    const float* Wl1_0 = (const float*)d_in[2];
    const float* Wl1_1 = (const float*)d_in[3];
    const float* Wl2_0 = (const float*)d_in[4];
    const float* bl2_0 = (const float*)d_in[5];
    const float* Wl2_1 = (const float*)d_in[6];
    const float* W00   = (const float*)d_in[7];
    const float* W11   = (const float*)d_in[8];
    const float* Wm1   = (const float*)d_in[9];
    const float* Wm2   = (const float*)d_in[10];
    const float* Wm3   = (const float*)d_in[11];
    const float* Wm4   = (const float*)d_in[12];
    const float* Wo0a  = (const float*)d_in[13];
    const float* Wo0b  = (const float*)d_in[14];
    const float* Wo1a  = (const float*)d_in[15];
    const float* Wo1b  = (const float*)d_in[16];
    float* out = (float*)d_out;

    // SILU_CST: input-independent — replicate reference quadrature on host (f64).
    double dz = 24.0 / 200000.0;
    double m2 = 0.0;
    const double inv_sqrt2pi = 0.3989422804014326779399460599343818684759;
    for (int i = 0; i <= 200000; i++) {
        double z = -12.0 + i * dz;
        double s = z / (1.0 + exp(-z));
        m2 += s * s * exp(-0.5 * z * z) * inv_sqrt2pi;
    }
    m2 *= dz;
    float silu_cst = (float)(1.0 / sqrt(m2));

    cudaFuncSetAttribute(main_kernel, cudaFuncAttributeMaxDynamicSharedMemorySize, SMEM_BYTES);

    precompute_kernel<<<36, 256>>>(W00, W11, Wl2_0, bl2_0, Wl2_1);
    main_kernel<<<NCTAS, NTH, SMEM_BYTES>>>(nf, pot, Wl1_0, Wl1_1,
                                            Wm1, Wm2, Wm3, Wm4,
                                            Wo0a, Wo0b, Wo1a, Wo1b, out, silu_cst);
}